// round 8
// baseline (speedup 1.0000x reference)
#include <cuda_runtime.h>
#include <cuda_bf16.h>
#include <cstdint>

#define BATCH 8
#define CH    128
#define HW    256
#define HS    64
#define NN    4096   // HS*HS

// Folded into Q at downsample: 0.25 (2x2 mean) * log2(e)/sqrt(128).
#define QSCALE_DS 0.031879358f

// Scratch (__device__ globals: allocation-free rule). L2-resident (8 MB each).
__device__ __nv_bfloat16 g_q[(size_t)BATCH*NN*CH];   // [b][n][c], pre-scaled
__device__ __nv_bfloat16 g_k[(size_t)BATCH*NN*CH];   // [b][n][c]
__device__ __nv_bfloat16 g_o[(size_t)BATCH*NN*CH];   // [b][n][c]

static __device__ __forceinline__ unsigned smem_u32(const void* p) {
    return (unsigned)__cvta_generic_to_shared(p);
}
static __device__ __forceinline__ float ex2f(float x) {
    float y; asm("ex2.approx.ftz.f32 %0, %1;" : "=f"(y) : "f"(x)); return y;
}
static __device__ __forceinline__ void cp16(unsigned dst, const void* src) {
    asm volatile("cp.async.cg.shared.global [%0], [%1], 16;\n" :: "r"(dst), "l"(src) : "memory");
}
static __device__ __forceinline__ void cp_commit() {
    asm volatile("cp.async.commit_group;\n" ::: "memory");
}
template<int N>
static __device__ __forceinline__ void cp_wait() {
    asm volatile("cp.async.wait_group %0;\n" :: "n"(N) : "memory");
}
static __device__ __forceinline__ void ldsm_x4(unsigned& r0, unsigned& r1, unsigned& r2, unsigned& r3, unsigned a) {
    asm volatile("ldmatrix.sync.aligned.m8n8.x4.shared.b16 {%0,%1,%2,%3}, [%4];\n"
        : "=r"(r0), "=r"(r1), "=r"(r2), "=r"(r3) : "r"(a));
}
static __device__ __forceinline__ void ldsm_x4_t(unsigned& r0, unsigned& r1, unsigned& r2, unsigned& r3, unsigned a) {
    asm volatile("ldmatrix.sync.aligned.m8n8.x4.trans.shared.b16 {%0,%1,%2,%3}, [%4];\n"
        : "=r"(r0), "=r"(r1), "=r"(r2), "=r"(r3) : "r"(a));
}
static __device__ __forceinline__ void mma16816(float* d, const unsigned* a, unsigned b0, unsigned b1) {
    asm volatile("mma.sync.aligned.m16n8k16.row.col.f32.bf16.bf16.f32 "
        "{%0,%1,%2,%3}, {%4,%5,%6,%7}, {%8,%9}, {%0,%1,%2,%3};\n"
        : "+f"(d[0]), "+f"(d[1]), "+f"(d[2]), "+f"(d[3])
        : "r"(a[0]), "r"(a[1]), "r"(a[2]), "r"(a[3]), "r"(b0), "r"(b1));
}

// Dynamic smem (bf16 elements):
//   sQ  : 128 x 128 @ 0        (32 KB)
//   sK0 :  64 x 128 @ 16384    (16 KB)
//   sK1 :  64 x 128 @ 24576    (16 KB)
#define SQ_OFF  0
#define SK_OFF(buf) (16384 + (buf)*8192)
#define SMEM_DYN (65536 + 1024)

// ---------------------------------------------------------------------------
// Kernel 1: 0.25x bilinear downsample == mean of center 2x2 block.
// g_q gets QSCALE_DS folded in; g_k gets plain 0.25. grid (64,8), 256 thr.
// ---------------------------------------------------------------------------
__global__ __launch_bounds__(256) void ds_kernel(const float* __restrict__ fw,
                                                 const float* __restrict__ fn) {
    __shared__ __nv_bfloat16 sout[64][132];
    const int i   = blockIdx.x;
    const int b   = blockIdx.y;
    const int tid = threadIdx.x;
    const int j   = tid & 63;
    const int cq  = tid >> 6;

    for (int pass = 0; pass < 2; ++pass) {
        const float* src = pass ? fn : fw;
        __nv_bfloat16* dst = pass ? g_k : g_q;
        const float sc = pass ? 0.25f : QSCALE_DS;

        #pragma unroll
        for (int cb = 0; cb < CH; cb += 4) {
            const int c = cb + cq;
            const float* p = src + (((size_t)(b*CH + c))*HW + (4*i + 1))*HW + (4*j + 1);
            sout[j][c] = __float2bfloat16(sc * (p[0] + p[1] + p[HW] + p[HW + 1]));
        }
        __syncthreads();
        __nv_bfloat16* dbase = dst + ((size_t)b*NN + (size_t)i*64)*CH;
        for (int t = tid; t < 64*32; t += 256) {
            const int j2 = t >> 5, cg = t & 31;
            *(uint2*)&dbase[j2*CH + cg*4] = *(const uint2*)&sout[j2][cg*4];
        }
        __syncthreads();
    }
}

// ---------------------------------------------------------------------------
// Kernel 2: flash attention, no-max softmax (logits bounded), V = K.
// grid (32, 8), 256 threads = 8 warps x 16 query rows. occ=2 -> single wave.
// Q resident in smem; K tiles double-buffered via cp.async.
// Each 64-row K tile processed as two 32-row chunks to keep regs < 128
// (spill-free at occupancy 2).
// ---------------------------------------------------------------------------
__global__ __launch_bounds__(256, 2) void attn_kernel() {
    extern __shared__ __align__(16) char dsm[];
    __nv_bfloat16* sm = (__nv_bfloat16*)(((unsigned long long)dsm + 1023ull) & ~1023ull);
    __nv_bfloat16* sQ = sm + SQ_OFF;

    const int b    = blockIdx.y;
    const int qt   = blockIdx.x;
    const int tid  = threadIdx.x;
    const int warp = tid >> 5;
    const int lane = tid & 31;
    const int g    = lane >> 2;     // row within 8-group
    const int tg   = lane & 3;
    const int t4   = lane >> 3;     // 0..3
    const int r8   = lane & 7;

    // ---- prologue: stage Q (128x128) and K tile 0 (64x128), swizzled ----
    {
        const __nv_bfloat16* Qg = g_q + ((size_t)b*NN + (size_t)qt*128)*CH;
        #pragma unroll
        for (int i = tid; i < 2048; i += 256) {     // 128 rows x 16 chunks
            const int r = i >> 4, k = i & 15;
            cp16(smem_u32(sQ + r*128 + ((k ^ (r & 7)) << 3)), Qg + (size_t)r*CH + k*8);
        }
        const __nv_bfloat16* Kg = g_k + (size_t)b*NN*CH;
        __nv_bfloat16* sK0 = sm + SK_OFF(0);
        #pragma unroll
        for (int i = tid; i < 1024; i += 256) {     // 64 rows x 16 chunks
            const int r = i >> 4, k = i & 15;
            cp16(smem_u32(sK0 + r*128 + ((k ^ (r & 7)) << 3)), Kg + (size_t)r*CH + k*8);
        }
        cp_commit();
    }

    float Oacc[16][4];
    #pragma unroll
    for (int t = 0; t < 16; ++t) { Oacc[t][0]=0.f; Oacc[t][1]=0.f; Oacc[t][2]=0.f; Oacc[t][3]=0.f; }
    float l0 = 0.f, l1 = 0.f;

    const __nv_bfloat16* Kbase = g_k + (size_t)b*NN*CH;
    const int qAddrRow = warp*16 + (lane & 15);     // ldmatrix A source row
    const int qAddrHi  = lane >> 4;                 // 0/1 -> col-chunk half

    for (int kt = 0; kt < 64; ++kt) {
        // prefetch next K tile into the other buffer
        if (kt < 63) {
            const __nv_bfloat16* Kg = Kbase + (size_t)(kt + 1)*64*CH;
            __nv_bfloat16* sKn = sm + SK_OFF((kt + 1) & 1);
            #pragma unroll
            for (int i = tid; i < 1024; i += 256) {
                const int r = i >> 4, k = i & 15;
                cp16(smem_u32(sKn + r*128 + ((k ^ (r & 7)) << 3)), Kg + (size_t)r*CH + k*8);
            }
            cp_commit();
            cp_wait<1>();
        } else {
            cp_wait<0>();
        }
        __syncthreads();

        const __nv_bfloat16* sK = sm + SK_OFF(kt & 1);

        // ---- two 32-kv-row chunks: S -> exp -> PV, small live set ----
        #pragma unroll 1
        for (int c2 = 0; c2 < 2; ++c2) {
            // S = Q * Kchunk^T  (m16 x n32 x k128 per warp)
            float sacc[4][4];
            #pragma unroll
            for (int t = 0; t < 4; ++t) { sacc[t][0]=0.f; sacc[t][1]=0.f; sacc[t][2]=0.f; sacc[t][3]=0.f; }

            #pragma unroll
            for (int kc = 0; kc < 8; ++kc) {
                unsigned aQ[4];
                {
                    const int kchunk = kc*2 + qAddrHi;
                    unsigned addr = smem_u32(&sQ[qAddrRow*128 + ((kchunk ^ (qAddrRow & 7)) << 3)]);
                    ldsm_x4(aQ[0], aQ[1], aQ[2], aQ[3], addr);
                }
                #pragma unroll
                for (int p2 = 0; p2 < 2; ++p2) {
                    const int m  = c2*32 + (2*p2 + (t4 >> 1))*8 + r8;
                    const int cc = kc*16 + (t4 & 1)*8;
                    unsigned addr = smem_u32(&sK[m*128 + (((cc >> 3) ^ (m & 7)) << 3)]);
                    unsigned r0, r1, r2, r3;
                    ldsm_x4(r0, r1, r2, r3, addr);
                    mma16816(sacc[2*p2],     aQ, r0, r1);
                    mma16816(sacc[2*p2 + 1], aQ, r2, r3);
                }
            }

            // p = exp2(s)  (log2e/sqrt(C) folded into Q); no max, no rescale
            unsigned aP[2][4];
            #pragma unroll
            for (int t = 0; t < 4; ++t) {
                const float p0 = ex2f(sacc[t][0]);
                const float p1 = ex2f(sacc[t][1]);
                const float p2 = ex2f(sacc[t][2]);
                const float p3 = ex2f(sacc[t][3]);
                l0 += p0 + p1;
                l1 += p2 + p3;
                const int kk = t >> 1, hi = t & 1;
                __nv_bfloat162 w01 = __floats2bfloat162_rn(p0, p1);
                __nv_bfloat162 w23 = __floats2bfloat162_rn(p2, p3);
                aP[kk][hi*2 + 0] = *reinterpret_cast<unsigned*>(&w01);
                aP[kk][hi*2 + 1] = *reinterpret_cast<unsigned*>(&w23);
            }

            // O += P * Vchunk (V = K), B frags via ldmatrix.trans
            #pragma unroll
            for (int kk = 0; kk < 2; ++kk) {
                #pragma unroll
                for (int cp = 0; cp < 8; ++cp) {
                    const int m  = (c2*2 + kk)*16 + (t4 & 1)*8 + r8;
                    const int cc = (cp*2 + (t4 >> 1))*8;
                    unsigned addr = smem_u32(&sK[m*128 + (((cc >> 3) ^ (m & 7)) << 3)]);
                    unsigned r0, r1, r2, r3;
                    ldsm_x4_t(r0, r1, r2, r3, addr);
                    mma16816(Oacc[2*cp],     aP[kk], r0, r1);
                    mma16816(Oacc[2*cp + 1], aP[kk], r2, r3);
                }
            }
        }
        __syncthreads();
    }

    // ---- epilogue: reduce l across quad, normalize, store bf16 [b][n][c] ----
    l0 += __shfl_xor_sync(0xffffffffu, l0, 1);
    l0 += __shfl_xor_sync(0xffffffffu, l0, 2);
    l1 += __shfl_xor_sync(0xffffffffu, l1, 1);
    l1 += __shfl_xor_sync(0xffffffffu, l1, 2);
    const float inv0 = 1.f / l0;
    const float inv1 = 1.f / l1;

    const int qrow = qt*128 + warp*16;
    __nv_bfloat16* Ob = g_o + ((size_t)b*NN + qrow)*CH;
    #pragma unroll
    for (int ct = 0; ct < 16; ++ct) {
        __nv_bfloat162 v0 = __floats2bfloat162_rn(Oacc[ct][0]*inv0, Oacc[ct][1]*inv0);
        __nv_bfloat162 v1 = __floats2bfloat162_rn(Oacc[ct][2]*inv1, Oacc[ct][3]*inv1);
        *(__nv_bfloat162*)&Ob[(size_t)(g    )*CH + ct*8 + tg*2] = v0;
        *(__nv_bfloat162*)&Ob[(size_t)(g + 8)*CH + ct*8 + tg*2] = v1;
    }
}

// ---------------------------------------------------------------------------
// Kernel 3: 4x bilinear upsample of g_o + residual add. grid (256,8), 256 thr.
// ---------------------------------------------------------------------------
__global__ __launch_bounds__(256) void up_kernel(const float* __restrict__ fw,
                                                 float* __restrict__ out) {
    __shared__ __nv_bfloat16 s[2][CH][68];
    const int Y   = blockIdx.x;
    const int b   = blockIdx.y;
    const int tid = threadIdx.x;

    const float yf = (Y + 0.5f)*0.25f - 0.5f;
    const int   iy = (int)floorf(yf);
    const float ty = yf - (float)iy;
    const int r0 = max(iy, 0), r1 = min(iy + 1, HS - 1);

    for (int t = tid; t < 2*64*32; t += 256) {
        const int yy  = t >> 11;
        const int rem = t & 2047;
        const int x   = rem >> 5;
        const int cg  = rem & 31;
        const int row = yy ? r1 : r0;
        const __nv_bfloat16* p = g_o + ((size_t)b*NN + (size_t)row*64 + x)*CH + cg*4;
        uint2 v = *(const uint2*)p;
        __nv_bfloat16 tmp[4];
        *(uint2*)tmp = v;
        s[yy][cg*4 + 0][x] = tmp[0];
        s[yy][cg*4 + 1][x] = tmp[1];
        s[yy][cg*4 + 2][x] = tmp[2];
        s[yy][cg*4 + 3][x] = tmp[3];
    }
    __syncthreads();

    const int X = tid;
    const float xf = (X + 0.5f)*0.25f - 0.5f;
    const int   ix = (int)floorf(xf);
    const float tx = xf - (float)ix;
    const int x0 = max(ix, 0), x1 = min(ix + 1, HS - 1);
    const float w00 = (1.f - ty)*(1.f - tx), w01 = (1.f - ty)*tx;
    const float w10 = ty*(1.f - tx),         w11 = ty*tx;

    #pragma unroll 4
    for (int c = 0; c < CH; ++c) {
        const float v = w00*__bfloat162float(s[0][c][x0]) + w01*__bfloat162float(s[0][c][x1])
                      + w10*__bfloat162float(s[1][c][x0]) + w11*__bfloat162float(s[1][c][x1]);
        const size_t idx = (((size_t)(b*CH + c))*HW + Y)*HW + X;
        out[idx] = fw[idx] + v;
    }
}

// ---------------------------------------------------------------------------
extern "C" void kernel_launch(void* const* d_in, const int* in_sizes, int n_in,
                              void* d_out, int out_size) {
    (void)in_sizes; (void)n_in; (void)out_size;
    const float* fw = (const float*)d_in[0];   // feat_wide
    const float* fn = (const float*)d_in[1];   // feat_narrow
    float* out = (float*)d_out;

    cudaFuncSetAttribute(attn_kernel, cudaFuncAttributeMaxDynamicSharedMemorySize, SMEM_DYN);

    ds_kernel<<<dim3(64, 8), 256>>>(fw, fn);
    attn_kernel<<<dim3(32, 8), 256, SMEM_DYN>>>();
    up_kernel<<<dim3(256, 8), 256>>>(fw, out);
}

// round 9
// speedup vs baseline: 1.3824x; 1.3824x over previous
#include <cuda_runtime.h>
#include <cuda_bf16.h>
#include <cstdint>

#define BATCH 8
#define CH    128
#define HW    256
#define HS    64
#define NN    4096   // HS*HS

// Folded into Q at downsample: 0.25 (2x2 mean) * log2(e)/sqrt(128).
#define QSCALE_DS 0.031879358f

// Scratch (__device__ globals: allocation-free rule). L2-resident (8 MB each).
__device__ __nv_bfloat16 g_q[(size_t)BATCH*NN*CH];   // [b][n][c], pre-scaled
__device__ __nv_bfloat16 g_k[(size_t)BATCH*NN*CH];   // [b][n][c]
__device__ __nv_bfloat16 g_o[(size_t)BATCH*NN*CH];   // [b][n][c]

static __device__ __forceinline__ unsigned smem_u32(const void* p) {
    return (unsigned)__cvta_generic_to_shared(p);
}
static __device__ __forceinline__ float ex2f(float x) {
    float y; asm("ex2.approx.ftz.f32 %0, %1;" : "=f"(y) : "f"(x)); return y;
}
static __device__ __forceinline__ void cp16(unsigned dst, const void* src) {
    asm volatile("cp.async.cg.shared.global [%0], [%1], 16;\n" :: "r"(dst), "l"(src) : "memory");
}
static __device__ __forceinline__ void cp_commit() {
    asm volatile("cp.async.commit_group;\n" ::: "memory");
}
template<int N>
static __device__ __forceinline__ void cp_wait() {
    asm volatile("cp.async.wait_group %0;\n" :: "n"(N) : "memory");
}
static __device__ __forceinline__ void ldsm_x4(unsigned& r0, unsigned& r1, unsigned& r2, unsigned& r3, unsigned a) {
    asm volatile("ldmatrix.sync.aligned.m8n8.x4.shared.b16 {%0,%1,%2,%3}, [%4];\n"
        : "=r"(r0), "=r"(r1), "=r"(r2), "=r"(r3) : "r"(a));
}
static __device__ __forceinline__ void ldsm_x4_t(unsigned& r0, unsigned& r1, unsigned& r2, unsigned& r3, unsigned a) {
    asm volatile("ldmatrix.sync.aligned.m8n8.x4.trans.shared.b16 {%0,%1,%2,%3}, [%4];\n"
        : "=r"(r0), "=r"(r1), "=r"(r2), "=r"(r3) : "r"(a));
}
static __device__ __forceinline__ void mma16816(float* d, const unsigned* a, unsigned b0, unsigned b1) {
    asm volatile("mma.sync.aligned.m16n8k16.row.col.f32.bf16.bf16.f32 "
        "{%0,%1,%2,%3}, {%4,%5,%6,%7}, {%8,%9}, {%0,%1,%2,%3};\n"
        : "+f"(d[0]), "+f"(d[1]), "+f"(d[2]), "+f"(d[3])
        : "r"(a[0]), "r"(a[1]), "r"(a[2]), "r"(a[3]), "r"(b0), "r"(b1));
}

// Dynamic smem (bf16 elements):
//   sQ  : 128 x 128 @ 0        (32 KB)
//   sK0 :  64 x 128 @ 16384    (16 KB)
//   sK1 :  64 x 128 @ 24576    (16 KB)
#define SQ_OFF  0
#define SK_OFF(buf) (16384 + (buf)*8192)
#define SMEM_DYN (65536 + 1024)

// ---------------------------------------------------------------------------
// Kernel 1: 0.25x bilinear downsample == mean of center 2x2 block.
// g_q gets QSCALE_DS folded in; g_k gets plain 0.25.
// grid (64, 8, 4) = (out_row i, batch, channel-quarter), 256 threads.
// 2048 CTAs -> ~8 CTAs/SM (was 512 -> 3.5, grid-limited at 40% occ).
// ---------------------------------------------------------------------------
__global__ __launch_bounds__(256) void ds_kernel(const float* __restrict__ fw,
                                                 const float* __restrict__ fn) {
    __shared__ __nv_bfloat16 sout[64][36];
    const int i   = blockIdx.x;
    const int b   = blockIdx.y;
    const int c0  = blockIdx.z * 32;          // channel-quarter base
    const int tid = threadIdx.x;
    const int j   = tid & 63;
    const int cq  = tid >> 6;

    for (int pass = 0; pass < 2; ++pass) {
        const float* src = pass ? fn : fw;
        __nv_bfloat16* dst = pass ? g_k : g_q;
        const float sc = pass ? 0.25f : QSCALE_DS;

        #pragma unroll
        for (int cb = 0; cb < 32; cb += 4) {
            const int cl = cb + cq;           // local channel 0..31
            const float* p = src + (((size_t)(b*CH + c0 + cl))*HW + (4*i + 1))*HW + (4*j + 1);
            sout[j][cl] = __float2bfloat16(sc * (p[0] + p[1] + p[HW] + p[HW + 1]));
        }
        __syncthreads();
        __nv_bfloat16* dbase = dst + ((size_t)b*NN + (size_t)i*64)*CH + c0;
        #pragma unroll
        for (int t = tid; t < 64*8; t += 256) {
            const int j2 = t >> 3, cg = t & 7;
            *(uint2*)&dbase[(size_t)j2*CH + cg*4] = *(const uint2*)&sout[j2][cg*4];
        }
        __syncthreads();
    }
}

// ---------------------------------------------------------------------------
// Kernel 2: flash attention, no-max softmax (logits bounded), V = K.
// grid (32, 8), 256 threads = 8 warps x 16 query rows. occ=2 -> single wave.
// Q resident in smem; K tiles double-buffered via cp.async.
// (Exact round-6 structure — known 384us baseline.)
// ---------------------------------------------------------------------------
__global__ __launch_bounds__(256, 2) void attn_kernel() {
    extern __shared__ __align__(16) char dsm[];
    __nv_bfloat16* sm = (__nv_bfloat16*)(((unsigned long long)dsm + 1023ull) & ~1023ull);
    __nv_bfloat16* sQ = sm + SQ_OFF;

    const int b    = blockIdx.y;
    const int qt   = blockIdx.x;
    const int tid  = threadIdx.x;
    const int warp = tid >> 5;
    const int lane = tid & 31;
    const int g    = lane >> 2;     // row within 8-group
    const int tg   = lane & 3;
    const int t4   = lane >> 3;     // 0..3
    const int r8   = lane & 7;

    // ---- prologue: stage Q (128x128) and K tile 0 (64x128), swizzled ----
    {
        const __nv_bfloat16* Qg = g_q + ((size_t)b*NN + (size_t)qt*128)*CH;
        #pragma unroll
        for (int i = tid; i < 2048; i += 256) {     // 128 rows x 16 chunks
            const int r = i >> 4, k = i & 15;
            cp16(smem_u32(sQ + r*128 + ((k ^ (r & 7)) << 3)), Qg + (size_t)r*CH + k*8);
        }
        const __nv_bfloat16* Kg = g_k + (size_t)b*NN*CH;
        __nv_bfloat16* sK0 = sm + SK_OFF(0);
        #pragma unroll
        for (int i = tid; i < 1024; i += 256) {     // 64 rows x 16 chunks
            const int r = i >> 4, k = i & 15;
            cp16(smem_u32(sK0 + r*128 + ((k ^ (r & 7)) << 3)), Kg + (size_t)r*CH + k*8);
        }
        cp_commit();
    }

    float Oacc[16][4];
    #pragma unroll
    for (int t = 0; t < 16; ++t) { Oacc[t][0]=0.f; Oacc[t][1]=0.f; Oacc[t][2]=0.f; Oacc[t][3]=0.f; }
    float l0 = 0.f, l1 = 0.f;

    const __nv_bfloat16* Kbase = g_k + (size_t)b*NN*CH;
    const int qAddrRow = warp*16 + (lane & 15);     // ldmatrix A source row
    const int qAddrHi  = lane >> 4;                 // 0/1 -> col-chunk half

    for (int kt = 0; kt < 64; ++kt) {
        // prefetch next K tile into the other buffer
        if (kt < 63) {
            const __nv_bfloat16* Kg = Kbase + (size_t)(kt + 1)*64*CH;
            __nv_bfloat16* sKn = sm + SK_OFF((kt + 1) & 1);
            #pragma unroll
            for (int i = tid; i < 1024; i += 256) {
                const int r = i >> 4, k = i & 15;
                cp16(smem_u32(sKn + r*128 + ((k ^ (r & 7)) << 3)), Kg + (size_t)r*CH + k*8);
            }
            cp_commit();
            cp_wait<1>();
        } else {
            cp_wait<0>();
        }
        __syncthreads();

        const __nv_bfloat16* sK = sm + SK_OFF(kt & 1);

        // ---- S = Q * Ktile^T  (m16 x n64 x k128 per warp) ----
        float sacc[8][4];
        #pragma unroll
        for (int t = 0; t < 8; ++t) { sacc[t][0]=0.f; sacc[t][1]=0.f; sacc[t][2]=0.f; sacc[t][3]=0.f; }

        #pragma unroll
        for (int kc = 0; kc < 8; ++kc) {
            unsigned aQ[4];
            {
                const int kchunk = kc*2 + qAddrHi;
                unsigned addr = smem_u32(&sQ[qAddrRow*128 + ((kchunk ^ (qAddrRow & 7)) << 3)]);
                ldsm_x4(aQ[0], aQ[1], aQ[2], aQ[3], addr);
            }
            #pragma unroll
            for (int p2 = 0; p2 < 4; ++p2) {
                const int m  = (2*p2 + (t4 >> 1))*8 + r8;
                const int cc = kc*16 + (t4 & 1)*8;
                unsigned addr = smem_u32(&sK[m*128 + (((cc >> 3) ^ (m & 7)) << 3)]);
                unsigned r0, r1, r2, r3;
                ldsm_x4(r0, r1, r2, r3, addr);
                mma16816(sacc[2*p2],     aQ, r0, r1);
                mma16816(sacc[2*p2 + 1], aQ, r2, r3);
            }
        }

        // ---- p = exp2(s)  (log2e/sqrt(C) folded into Q); no max, no rescale ----
        unsigned aP[4][4];
        #pragma unroll
        for (int t = 0; t < 8; ++t) {
            const float p0 = ex2f(sacc[t][0]);
            const float p1 = ex2f(sacc[t][1]);
            const float p2 = ex2f(sacc[t][2]);
            const float p3 = ex2f(sacc[t][3]);
            l0 += p0 + p1;
            l1 += p2 + p3;
            const int kk = t >> 1, hi = t & 1;
            __nv_bfloat162 w01 = __floats2bfloat162_rn(p0, p1);
            __nv_bfloat162 w23 = __floats2bfloat162_rn(p2, p3);
            aP[kk][hi*2 + 0] = *reinterpret_cast<unsigned*>(&w01);
            aP[kk][hi*2 + 1] = *reinterpret_cast<unsigned*>(&w23);
        }

        // ---- O += P * Vtile (V = K), B frags via ldmatrix.trans ----
        #pragma unroll
        for (int kk = 0; kk < 4; ++kk) {
            #pragma unroll
            for (int cp = 0; cp < 8; ++cp) {
                const int m  = kk*16 + (t4 & 1)*8 + r8;
                const int cc = (cp*2 + (t4 >> 1))*8;
                unsigned addr = smem_u32(&sK[m*128 + (((cc >> 3) ^ (m & 7)) << 3)]);
                unsigned r0, r1, r2, r3;
                ldsm_x4_t(r0, r1, r2, r3, addr);
                mma16816(Oacc[2*cp],     aP[kk], r0, r1);
                mma16816(Oacc[2*cp + 1], aP[kk], r2, r3);
            }
        }
        __syncthreads();
    }

    // ---- epilogue: reduce l across quad, normalize, store bf16 [b][n][c] ----
    l0 += __shfl_xor_sync(0xffffffffu, l0, 1);
    l0 += __shfl_xor_sync(0xffffffffu, l0, 2);
    l1 += __shfl_xor_sync(0xffffffffu, l1, 1);
    l1 += __shfl_xor_sync(0xffffffffu, l1, 2);
    const float inv0 = 1.f / l0;
    const float inv1 = 1.f / l1;

    const int qrow = qt*128 + warp*16;
    __nv_bfloat16* Ob = g_o + ((size_t)b*NN + qrow)*CH;
    #pragma unroll
    for (int ct = 0; ct < 16; ++ct) {
        __nv_bfloat162 v0 = __floats2bfloat162_rn(Oacc[ct][0]*inv0, Oacc[ct][1]*inv0);
        __nv_bfloat162 v1 = __floats2bfloat162_rn(Oacc[ct][2]*inv1, Oacc[ct][3]*inv1);
        *(__nv_bfloat162*)&Ob[(size_t)(g    )*CH + ct*8 + tg*2] = v0;
        *(__nv_bfloat162*)&Ob[(size_t)(g + 8)*CH + ct*8 + tg*2] = v1;
    }
}

// ---------------------------------------------------------------------------
// Kernel 3: 4x bilinear upsample of g_o + residual add. grid (256,8), 256 thr.
// ---------------------------------------------------------------------------
__global__ __launch_bounds__(256) void up_kernel(const float* __restrict__ fw,
                                                 float* __restrict__ out) {
    __shared__ __nv_bfloat16 s[2][CH][68];
    const int Y   = blockIdx.x;
    const int b   = blockIdx.y;
    const int tid = threadIdx.x;

    const float yf = (Y + 0.5f)*0.25f - 0.5f;
    const int   iy = (int)floorf(yf);
    const float ty = yf - (float)iy;
    const int r0 = max(iy, 0), r1 = min(iy + 1, HS - 1);

    for (int t = tid; t < 2*64*32; t += 256) {
        const int yy  = t >> 11;
        const int rem = t & 2047;
        const int x   = rem >> 5;
        const int cg  = rem & 31;
        const int row = yy ? r1 : r0;
        const __nv_bfloat16* p = g_o + ((size_t)b*NN + (size_t)row*64 + x)*CH + cg*4;
        uint2 v = *(const uint2*)p;
        __nv_bfloat16 tmp[4];
        *(uint2*)tmp = v;
        s[yy][cg*4 + 0][x] = tmp[0];
        s[yy][cg*4 + 1][x] = tmp[1];
        s[yy][cg*4 + 2][x] = tmp[2];
        s[yy][cg*4 + 3][x] = tmp[3];
    }
    __syncthreads();

    const int X = tid;
    const float xf = (X + 0.5f)*0.25f - 0.5f;
    const int   ix = (int)floorf(xf);
    const float tx = xf - (float)ix;
    const int x0 = max(ix, 0), x1 = min(ix + 1, HS - 1);
    const float w00 = (1.f - ty)*(1.f - tx), w01 = (1.f - ty)*tx;
    const float w10 = ty*(1.f - tx),         w11 = ty*tx;

    #pragma unroll 4
    for (int c = 0; c < CH; ++c) {
        const float v = w00*__bfloat162float(s[0][c][x0]) + w01*__bfloat162float(s[0][c][x1])
                      + w10*__bfloat162float(s[1][c][x0]) + w11*__bfloat162float(s[1][c][x1]);
        const size_t idx = (((size_t)(b*CH + c))*HW + Y)*HW + X;
        out[idx] = fw[idx] + v;
    }
}

// ---------------------------------------------------------------------------
extern "C" void kernel_launch(void* const* d_in, const int* in_sizes, int n_in,
                              void* d_out, int out_size) {
    (void)in_sizes; (void)n_in; (void)out_size;
    const float* fw = (const float*)d_in[0];   // feat_wide
    const float* fn = (const float*)d_in[1];   // feat_narrow
    float* out = (float*)d_out;

    cudaFuncSetAttribute(attn_kernel, cudaFuncAttributeMaxDynamicSharedMemorySize, SMEM_DYN);

    ds_kernel<<<dim3(64, 8, 4), 256>>>(fw, fn);
    attn_kernel<<<dim3(32, 8), 256, SMEM_DYN>>>();
    up_kernel<<<dim3(256, 8), 256>>>(fw, out);
}